// round 17
// baseline (speedup 1.0000x reference)
#include <cuda_runtime.h>
#include <cuda_bf16.h>
#include <cuda_fp16.h>
#include <cstdint>
#include <math.h>

#define BB 2
#define SS 2048
#define TT (BB*SS)
#define HH 2048
#define NHQ 16
#define NKV 8
#define HD 128
#define INTER 8192
#define EPS 1e-6f

// ======================= scratch =======================
__device__ __align__(256) float g_res1 [(size_t)TT*HH];
__device__ __align__(256) float g_qkv  [(size_t)TT*4096];
__device__ float g_invf [64];

// single-fp16 activations
__device__ __align__(256) __half g_xn   [(size_t)TT*HH];
__device__ __align__(256) __half g_at   [(size_t)TT*HH];
__device__ __align__(256) __half g_hattn[(size_t)TT*HH];
__device__ __align__(256) __half g_h2   [(size_t)TT*HH];
__device__ __align__(256) __half g_ac   [(size_t)TT*INTER];

// flash operands
__device__ __align__(256) __half g_Qf [(size_t)TT*2048];
__device__ __align__(256) __half g_Kf [(size_t)TT*1024];
__device__ __align__(256) __half g_Vh [(size_t)TT*1024];   // [b][hk][d][s]

// single-fp16 transposed weights [N, K]
__device__ __align__(256) __half g_qkvT[(size_t)4096*HH];
__device__ __align__(256) __half g_woT [(size_t)HH*(NHQ*HD)];
__device__ __align__(256) __half g_guT [(size_t)(2*INTER)*HH];   // interleaved gate/up
__device__ __align__(256) __half g_wdT [(size_t)HH*INTER];

// ======================= PTX helpers =======================
__device__ __forceinline__ uint32_t s2u(const void* p) {
    uint32_t a;
    asm("{ .reg .u64 t; cvta.to.shared.u64 t, %1; cvt.u32.u64 %0, t; }" : "=r"(a) : "l"(p));
    return a;
}
__device__ __forceinline__ void cpasync16(uint32_t dst, const void* src) {
    asm volatile("cp.async.cg.shared.global [%0], [%1], 16;" :: "r"(dst), "l"(src) : "memory");
}
__device__ __forceinline__ void cp_commit() { asm volatile("cp.async.commit_group;" ::: "memory"); }
template<int N_>
__device__ __forceinline__ void cp_wait() { asm volatile("cp.async.wait_group %0;" :: "n"(N_) : "memory"); }
__device__ __forceinline__ void ldsm4(uint32_t* r, uint32_t addr) {
    asm volatile("ldmatrix.sync.aligned.m8n8.x4.shared.b16 {%0,%1,%2,%3}, [%4];"
                 : "=r"(r[0]), "=r"(r[1]), "=r"(r[2]), "=r"(r[3]) : "r"(addr));
}
__device__ __forceinline__ void mma_f16(float* d, const uint32_t* a, const uint32_t* b) {
    asm volatile(
        "mma.sync.aligned.m16n8k16.row.col.f32.f16.f16.f32 "
        "{%0,%1,%2,%3}, {%4,%5,%6,%7}, {%8,%9}, {%0,%1,%2,%3};"
        : "+f"(d[0]), "+f"(d[1]), "+f"(d[2]), "+f"(d[3])
        : "r"(a[0]), "r"(a[1]), "r"(a[2]), "r"(a[3]), "r"(b[0]), "r"(b[1]));
}
__device__ __forceinline__ void split_pack_h(uint32_t& ph, uint32_t& pl, float x, float y)
{
    __half hx = __float2half(x), hy = __float2half(y);
    __half2 h2 = __halves2half2(hx, hy);
    __half2 l2 = __halves2half2(__float2half(x - __half2float(hx)),
                                __float2half(y - __half2float(hy)));
    ph = *(uint32_t*)&h2; pl = *(uint32_t*)&l2;
}
__device__ __forceinline__ uint32_t soffG(int r, int u)   { return (uint32_t)(r*128 + ((u ^ (r & 7)) << 4)); }
__device__ __forceinline__ uint32_t soff256(int r, int u) { return (uint32_t)(r*256 + ((u ^ (r & 7)) << 4)); }

// ======================= fused add + RMSNorm (fp32+fp32 in, fp16 out) =======================
__global__ void add_rmsnorm_kernel(const float* __restrict__ a, const float* __restrict__ b,
                                   const float* __restrict__ w, float* __restrict__ res,
                                   __half* __restrict__ oh)
{
    int t = blockIdx.x, tid = threadIdx.x;
    const float4* a4 = (const float4*)(a + (size_t)t * HH);
    const float4* b4 = (const float4*)(b + (size_t)t * HH);
    float4* r4 = (float4*)(res + (size_t)t * HH);
    const float4* w4 = (const float4*)w;
    __half2* oh2 = (__half2*)(oh + (size_t)t * HH);

    float4 vv[2];
    float ss = 0.f;
#pragma unroll
    for (int ii = 0; ii < 2; ii++) {
        int idx = tid + ii * 256;
        float4 x = a4[idx], y = b4[idx];
        x.x += y.x; x.y += y.y; x.z += y.z; x.w += y.w;
        r4[idx] = x; vv[ii] = x;
        ss += x.x*x.x + x.y*x.y + x.z*x.z + x.w*x.w;
    }
#pragma unroll
    for (int off = 16; off; off >>= 1) ss += __shfl_xor_sync(0xffffffffu, ss, off);
    __shared__ float sh[8];
    __shared__ float s_inv;
    if ((tid & 31) == 0) sh[tid >> 5] = ss;
    __syncthreads();
    if (tid == 0) {
        float s = 0.f;
#pragma unroll
        for (int i = 0; i < 8; i++) s += sh[i];
        s_inv = rsqrtf(s / (float)HH + EPS);
    }
    __syncthreads();
    float inv = s_inv;
#pragma unroll
    for (int ii = 0; ii < 2; ii++) {
        int idx = tid + ii * 256;
        float4 x = vv[ii], ww = w4[idx];
        oh2[idx*2]   = __floats2half2_rn(x.x*inv*ww.x, x.y*inv*ww.y);
        oh2[idx*2+1] = __floats2half2_rn(x.z*inv*ww.z, x.w*inv*ww.w);
    }
}

// variant: a is fp16 (hattn), b fp32 (res1)
__global__ void add_rmsnorm_h_kernel(const __half* __restrict__ a, const float* __restrict__ b,
                                     const float* __restrict__ w, float* __restrict__ res,
                                     __half* __restrict__ oh)
{
    int t = blockIdx.x, tid = threadIdx.x;
    const __half2* a2 = (const __half2*)(a + (size_t)t * HH);
    const float4* b4 = (const float4*)(b + (size_t)t * HH);
    float4* r4 = (float4*)(res + (size_t)t * HH);
    const float4* w4 = (const float4*)w;
    __half2* oh2 = (__half2*)(oh + (size_t)t * HH);

    float4 vv[2];
    float ss = 0.f;
#pragma unroll
    for (int ii = 0; ii < 2; ii++) {
        int idx = tid + ii * 256;
        float2 alo = __half22float2(a2[idx*2]);
        float2 ahi = __half22float2(a2[idx*2+1]);
        float4 y = b4[idx];
        float4 x = make_float4(alo.x + y.x, alo.y + y.y, ahi.x + y.z, ahi.y + y.w);
        r4[idx] = x; vv[ii] = x;
        ss += x.x*x.x + x.y*x.y + x.z*x.z + x.w*x.w;
    }
#pragma unroll
    for (int off = 16; off; off >>= 1) ss += __shfl_xor_sync(0xffffffffu, ss, off);
    __shared__ float sh[8];
    __shared__ float s_inv;
    if ((tid & 31) == 0) sh[tid >> 5] = ss;
    __syncthreads();
    if (tid == 0) {
        float s = 0.f;
#pragma unroll
        for (int i = 0; i < 8; i++) s += sh[i];
        s_inv = rsqrtf(s / (float)HH + EPS);
    }
    __syncthreads();
    float inv = s_inv;
#pragma unroll
    for (int ii = 0; ii < 2; ii++) {
        int idx = tid + ii * 256;
        float4 x = vv[ii], ww = w4[idx];
        oh2[idx*2]   = __floats2half2_rn(x.x*inv*ww.x, x.y*inv*ww.y);
        oh2[idx*2+1] = __floats2half2_rn(x.z*inv*ww.z, x.w*inv*ww.w);
    }
}

// ======================= weight split kernels =======================
__global__ void wsplit_kernel(const float* __restrict__ W, __half* __restrict__ Tw, int K, int N)
{
    __shared__ float tile[32][33];
    int k0 = blockIdx.y * 32, n0 = blockIdx.x * 32;
    int tx = threadIdx.x, ty = threadIdx.y;
#pragma unroll
    for (int j = 0; j < 4; j++)
        tile[ty + 8*j][tx] = W[(size_t)(k0 + ty + 8*j) * N + n0 + tx];
    __syncthreads();
#pragma unroll
    for (int j = 0; j < 4; j++) {
        int n = ty + 8*j;
        Tw[(size_t)(n0 + n) * K + k0 + tx] = __float2half(tile[tx][n]);
    }
}

__global__ void wsplit_qkv_kernel(const float* __restrict__ wq, const float* __restrict__ wk,
                                  const float* __restrict__ wv, __half* __restrict__ Tw)
{
    __shared__ float tile[32][33];
    int n0 = blockIdx.x * 32, k0 = blockIdx.y * 32;
    int tx = threadIdx.x, ty = threadIdx.y;
    if (blockIdx.x == 0 && blockIdx.y == 0) {
        int id = ty * 32 + tx;
        if (id < 64) g_invf[id] = (float)pow(1.0e6, -(double)id / 64.0);
    }
    int n = n0 + tx;
    const float* src; int nc, stride;
    if (n < 2048)      { src = wq; nc = n;        stride = 2048; }
    else if (n < 3072) { src = wk; nc = n - 2048; stride = 1024; }
    else               { src = wv; nc = n - 3072; stride = 1024; }
#pragma unroll
    for (int j = 0; j < 4; j++)
        tile[ty + 8*j][tx] = src[(size_t)(k0 + ty + 8*j) * stride + nc];
    __syncthreads();
#pragma unroll
    for (int j = 0; j < 4; j++) {
        int nn = n0 + ty + 8*j;
        Tw[(size_t)nn * HH + k0 + tx] = __float2half(tile[tx][ty + 8*j]);
    }
}

// gate_up interleave, coalesced: block handles 64 dest rows = 32 gate + 32 up cols
__global__ void wsplit_gu_kernel(const float* __restrict__ W, __half* __restrict__ Tw)
{
    __shared__ float tg[32][33];
    __shared__ float tu[32][33];
    int d0 = blockIdx.x * 64;            // dest rows [d0, d0+64)
    int g0 = d0 >> 1;                    // gate/up col base
    int k0 = blockIdx.y * 32;
    int tx = threadIdx.x, ty = threadIdx.y;
#pragma unroll
    for (int j = 0; j < 4; j++) {
        int k = k0 + ty + 8*j;
        tg[ty + 8*j][tx] = W[(size_t)k * 16384 + g0 + tx];
        tu[ty + 8*j][tx] = W[(size_t)k * 16384 + 8192 + g0 + tx];
    }
    __syncthreads();
#pragma unroll
    for (int j = 0; j < 8; j++) {
        int dr = ty + 8*j;               // dest row offset 0..63
        int sc = dr >> 1;
        float v = (dr & 1) ? tu[tx][sc] : tg[tx][sc];
        Tw[(size_t)(d0 + dr) * HH + k0 + tx] = __float2half(v);
    }
}

// ======================= single-fp16 GEMM (1 MMA/k16, BK=64, 2-stage, occ 2) =======================
#define G4_B  16384
#define G4_STAGE 32768
#define GEMM_SMEM (2*G4_STAGE)

__device__ __forceinline__ void g_load_stage(uint32_t sb, int s,
    const __half* __restrict__ A, const __half* __restrict__ Bw,
    int m0, int n0, int k0, int K, int tid)
{
    uint32_t st = sb + s * G4_STAGE;
#pragma unroll
    for (int j = 0; j < 8; j++) {
        int idx = j * 256 + tid;
        int seg = idx >> 10;
        int rem = idx & 1023;
        int r = rem >> 3, u = rem & 7;
        const __half* src = (seg == 0) ? (A + (size_t)(m0 + r) * K)
                                       : (Bw + (size_t)(n0 + r) * K);
        src += k0 + u * 8;
        cpasync16(st + seg * G4_B + soffG(r, u), src);
    }
    cp_commit();
}

// MODE 0: f32 out. MODE 1: qkv bias f32. MODE 2: fused SwiGLU -> fp16. MODE 3: f16 out.
template<int MODE>
__global__ __launch_bounds__(256, 2) void gemm_mma(
    const __half* __restrict__ A, const __half* __restrict__ Bw,
    const float* __restrict__ bq, const float* __restrict__ bk, const float* __restrict__ bv,
    float* __restrict__ C, __half* __restrict__ actH,
    int M, int N, int K)
{
    extern __shared__ char smc[];
    uint32_t sb = s2u(smc);
    int tid = threadIdx.x, lane = tid & 31, wid = tid >> 5;
    int wm = wid & 3, wn = wid >> 2;
    int m0 = blockIdx.y * 128, n0 = blockIdx.x * 128;

    float acc[2][8][4];
#pragma unroll
    for (int i = 0; i < 2; i++)
#pragma unroll
        for (int j = 0; j < 8; j++)
#pragma unroll
            for (int c = 0; c < 4; c++) acc[i][j][c] = 0.f;

    int rA = lane & 15, uA = lane >> 4;
    int rB = (lane & 7) | ((lane & 16) >> 1), uB = (lane >> 3) & 1;

    int nIter = K / 64;
    g_load_stage(sb, 0, A, Bw, m0, n0, 0, K, tid);
    g_load_stage(sb, 1, A, Bw, m0, n0, 64, K, tid);

    for (int it = 0; it < nIter; it++) {
        if (it + 1 < nIter) cp_wait<1>(); else cp_wait<0>();
        __syncthreads();

        uint32_t st = sb + (it & 1) * G4_STAGE;
#pragma unroll
        for (int ks = 0; ks < 4; ks++) {
            uint32_t ah[2][4];
#pragma unroll
            for (int mt = 0; mt < 2; mt++) {
                int row = wm * 32 + mt * 16 + rA;
                ldsm4(ah[mt], st + soffG(row, ks * 2 + uA));
            }
#pragma unroll
            for (int nt = 0; nt < 4; nt++) {
                int row = wn * 64 + nt * 16 + rB;
                uint32_t t4[4];
                ldsm4(t4, st + G4_B + soffG(row, ks * 2 + uB));
#pragma unroll
                for (int half = 0; half < 2; half++) {
                    int nf = nt * 2 + half;
                    uint32_t b2[2] = {t4[half*2], t4[half*2+1]};
#pragma unroll
                    for (int mt = 0; mt < 2; mt++)
                        mma_f16(acc[mt][nf], ah[mt], b2);
                }
            }
        }
        __syncthreads();
        if (it + 2 < nIter)
            g_load_stage(sb, it & 1, A, Bw, m0, n0, (it + 2) * 64, K, tid);
    }

    int crow = lane >> 2, ccol = (lane & 3) * 2;
#pragma unroll
    for (int mt = 0; mt < 2; mt++) {
#pragma unroll
        for (int nf = 0; nf < 8; nf++) {
            int r = m0 + wm * 32 + mt * 16 + crow;
            int cidx = n0 + wn * 64 + nf * 8 + ccol;
            if (MODE == 2) {
                int jj = cidx >> 1;
                float ga = acc[mt][nf][0], up = acc[mt][nf][1];
                float v0 = ga / (1.f + __expf(-ga)) * up;
                float gb = acc[mt][nf][2], ub = acc[mt][nf][3];
                float v1 = gb / (1.f + __expf(-gb)) * ub;
                actH[(size_t)r * INTER + jj] = __float2half(v0);
                actH[(size_t)(r + 8) * INTER + jj] = __float2half(v1);
            } else if (MODE == 3) {
                *(__half2*)(actH + (size_t)r * N + cidx) =
                    __floats2half2_rn(acc[mt][nf][0], acc[mt][nf][1]);
                *(__half2*)(actH + (size_t)(r + 8) * N + cidx) =
                    __floats2half2_rn(acc[mt][nf][2], acc[mt][nf][3]);
            } else {
                float b0 = 0.f, b1 = 0.f;
                if (MODE == 1) {
                    b0 = (cidx < 2048) ? bq[cidx] : ((cidx < 3072) ? bk[cidx - 2048] : bv[cidx - 3072]);
                    int c1 = cidx + 1;
                    b1 = (c1 < 2048) ? bq[c1] : ((c1 < 3072) ? bk[c1 - 2048] : bv[c1 - 3072]);
                }
                *(float2*)(C + (size_t)r * N + cidx) =
                    make_float2(acc[mt][nf][0] + b0, acc[mt][nf][1] + b1);
                *(float2*)(C + (size_t)(r + 8) * N + cidx) =
                    make_float2(acc[mt][nf][2] + b0, acc[mt][nf][3] + b1);
            }
        }
    }
}

// ======================= RoPE + convert Q,K to single fp16 =======================
__global__ void qkconv_kernel(const float* __restrict__ qkv, const int* __restrict__ pos,
    __half* __restrict__ Qf, __half* __restrict__ Kf)
{
    int idx = blockIdx.x * blockDim.x + threadIdx.x;
    int i = idx & 63;
    int rest = idx >> 6;
    int head = rest % 24;
    int t = rest / 24;
    if (t >= TT) return;
    const float* p = qkv + (size_t)t * 4096 + ((head < 16) ? head * 128 : 2048 + (head - 16) * 128);
    float ang = (float)pos[t] * g_invf[i];
    float sv, cv;
    sincosf(ang, &sv, &cv);
    float x1 = p[i], x2 = p[i + 64];
    float o1 = x1 * cv - x2 * sv;
    float o2 = x2 * cv + x1 * sv;
    __half* d;
    size_t dst;
    if (head < 16) { dst = (size_t)t * 2048 + head * 128;        d = Qf; }
    else           { dst = (size_t)t * 1024 + (head - 16) * 128; d = Kf; }
    d[dst + i]      = __float2half(o1);
    d[dst + i + 64] = __float2half(o2);
}

// ======================= V transpose (single fp16) =======================
__global__ void vconv_kernel(const float* __restrict__ qkv, __half* __restrict__ Vh)
{
    __shared__ float tile[32][33];
    int bhk = blockIdx.z;
    int b = bhk >> 3, hk = bhk & 7;
    int s0 = blockIdx.x * 32, d0 = blockIdx.y * 32;
    int tx = threadIdx.x, ty = threadIdx.y;
#pragma unroll
    for (int j = 0; j < 4; j++)
        tile[ty + 8*j][tx] = qkv[(size_t)(b * SS + s0 + ty + 8*j) * 4096 + 3072 + hk * 128 + d0 + tx];
    __syncthreads();
#pragma unroll
    for (int j = 0; j < 4; j++) {
        int d = d0 + ty + 8*j;
        size_t o = ((size_t)(b * NKV + hk) * HD + d) * SS + s0 + tx;
        Vh[o] = __float2half(tile[tx][ty + 8*j]);
    }
}

// ======================= tensor-core causal flash attention =======================
#define FQ 0
#define FST(s) (32768 + (s)*32768)
#define FK 0
#define FV 16384
#define FLASH_SMEM (32768 + 2*32768)

__global__ __launch_bounds__(256, 2) void flash_mma(
    const __half* __restrict__ Qf, const __half* __restrict__ Kf,
    const __half* __restrict__ Vh, __half* __restrict__ Oh)
{
    extern __shared__ char smc[];
    uint32_t sb = s2u(smc);
    int tid = threadIdx.x, lane = tid & 31, wid = tid >> 5;
    int qt = (gridDim.x - 1) - blockIdx.x;
    int h = blockIdx.y, b = blockIdx.z;
    int hk = h >> 1;
    int q0 = qt * 128;
    int rA = lane & 15, uA = lane >> 4;
    int rB = (lane & 7) | ((lane & 16) >> 1), uB = (lane >> 3) & 1;

#pragma unroll
    for (int j = 0; j < 8; j++) {
        int idx = j * 256 + tid;
        int r = idx >> 4, u = idx & 15;
        const __half* src = Qf + (size_t)(b * SS + q0 + r) * 2048 + h * 128 + u * 8;
        cpasync16(sb + FQ + soff256(r, u), src);
    }

    auto load_kv = [&](int buf, int kbase) {
        uint32_t st = sb + FST(buf);
#pragma unroll
        for (int j = 0; j < 4; j++) {
            int idx = j * 256 + tid;
            int r = idx >> 4, u = idx & 15;
            const __half* src = Kf + (size_t)(b * SS + kbase + r) * 1024 + hk * 128 + u * 8;
            cpasync16(st + FK + soff256(r, u), src);
        }
#pragma unroll
        for (int j = 0; j < 4; j++) {
            int idx = j * 256 + tid;
            int r = idx >> 3, u = idx & 7;
            const __half* src = Vh + ((size_t)(b * NKV + hk) * HD + r) * SS + kbase + u * 8;
            cpasync16(st + FV + soffG(r, u), src);
        }
        cp_commit();
    };
    load_kv(0, 0);

    float m0v = -1e30f, m1v = -1e30f, l0v = 0.f, l1v = 0.f;
    float accO[16][4];
#pragma unroll
    for (int i = 0; i < 16; i++)
#pragma unroll
        for (int c = 0; c < 4; c++) accO[i][c] = 0.f;

    const float sc = 0.08838834764831845f;
    int ktmax = 2 * qt + 1;
    int row0 = q0 + wid * 16 + (lane >> 2);

    for (int kt = 0; kt <= ktmax; kt++) {
        cp_wait<0>();
        __syncthreads();
        if (kt < ktmax) load_kv((kt + 1) & 1, (kt + 1) * 64);
        uint32_t st = sb + FST(kt & 1);

        float accS[8][4];
#pragma unroll
        for (int i = 0; i < 8; i++)
#pragma unroll
            for (int c = 0; c < 4; c++) accS[i][c] = 0.f;

#pragma unroll
        for (int j = 0; j < 8; j++) {
            uint32_t af[4];
            ldsm4(af, sb + FQ + soff256(wid * 16 + rA, 2 * j + uA));
            uint32_t bf[8][2];
#pragma unroll
            for (int nt = 0; nt < 4; nt++) {
                uint32_t t4[4];
                ldsm4(t4, st + FK + soff256(nt * 16 + rB, 2 * j + uB));
                bf[2*nt][0] = t4[0]; bf[2*nt][1] = t4[1];
                bf[2*nt+1][0] = t4[2]; bf[2*nt+1][1] = t4[3];
            }
#pragma unroll
            for (int nf = 0; nf < 8; nf++)
                mma_f16(accS[nf], af, bf[nf]);
        }

        int kbase = kt * 64;
        bool needmask = (kbase + 63) > row0;
#pragma unroll
        for (int nf = 0; nf < 8; nf++) {
#pragma unroll
            for (int e = 0; e < 4; e++) {
                float s = accS[nf][e] * sc;
                if (needmask) {
                    int cc = kbase + nf * 8 + (lane & 3) * 2 + (e & 1);
                    int rr = row0 + ((e >> 1) << 3);
                    if (cc > rr) s = -1e30f;
                }
                accS[nf][e] = s;
            }
        }
        float vm0 = -1e30f, vm1 = -1e30f;
#pragma unroll
        for (int nf = 0; nf < 8; nf++) {
            vm0 = fmaxf(vm0, fmaxf(accS[nf][0], accS[nf][1]));
            vm1 = fmaxf(vm1, fmaxf(accS[nf][2], accS[nf][3]));
        }
        vm0 = fmaxf(vm0, __shfl_xor_sync(0xffffffffu, vm0, 1));
        vm0 = fmaxf(vm0, __shfl_xor_sync(0xffffffffu, vm0, 2));
        vm1 = fmaxf(vm1, __shfl_xor_sync(0xffffffffu, vm1, 1));
        vm1 = fmaxf(vm1, __shfl_xor_sync(0xffffffffu, vm1, 2));
        float mn0 = fmaxf(m0v, vm0), mn1 = fmaxf(m1v, vm1);
        float c0 = __expf(m0v - mn0), c1 = __expf(m1v - mn1);
        float s0 = 0.f, s1 = 0.f;
#pragma unroll
        for (int nf = 0; nf < 8; nf++) {
            accS[nf][0] = __expf(accS[nf][0] - mn0); s0 += accS[nf][0];
            accS[nf][1] = __expf(accS[nf][1] - mn0); s0 += accS[nf][1];
            accS[nf][2] = __expf(accS[nf][2] - mn1); s1 += accS[nf][2];
            accS[nf][3] = __expf(accS[nf][3] - mn1); s1 += accS[nf][3];
        }
        s0 += __shfl_xor_sync(0xffffffffu, s0, 1);
        s0 += __shfl_xor_sync(0xffffffffu, s0, 2);
        s1 += __shfl_xor_sync(0xffffffffu, s1, 1);
        s1 += __shfl_xor_sync(0xffffffffu, s1, 2);
        l0v = l0v * c0 + s0; l1v = l1v * c1 + s1;
        m0v = mn0; m1v = mn1;
#pragma unroll
        for (int i = 0; i < 16; i++) {
            accO[i][0] *= c0; accO[i][1] *= c0;
            accO[i][2] *= c1; accO[i][3] *= c1;
        }

#pragma unroll
        for (int j2 = 0; j2 < 4; j2++) {
            uint32_t pah[4], pal[4];
            split_pack_h(pah[0], pal[0], accS[2*j2][0],   accS[2*j2][1]);
            split_pack_h(pah[1], pal[1], accS[2*j2][2],   accS[2*j2][3]);
            split_pack_h(pah[2], pal[2], accS[2*j2+1][0], accS[2*j2+1][1]);
            split_pack_h(pah[3], pal[3], accS[2*j2+1][2], accS[2*j2+1][3]);
#pragma unroll
            for (int nt = 0; nt < 8; nt++) {
                uint32_t voff = soffG(nt * 16 + rB, 2 * j2 + uB);
                uint32_t t4[4], v0[2], v1[2];
                ldsm4(t4, st + FV + voff);
                v0[0] = t4[0]; v0[1] = t4[1]; v1[0] = t4[2]; v1[1] = t4[3];
                mma_f16(accO[2*nt],   pah, v0);
                mma_f16(accO[2*nt],   pal, v0);
                mma_f16(accO[2*nt+1], pah, v1);
                mma_f16(accO[2*nt+1], pal, v1);
            }
        }
    }

    float inv0 = 1.0f / l0v, inv1 = 1.0f / l1v;
#pragma unroll
    for (int nf = 0; nf < 16; nf++) {
        int d = nf * 8 + (lane & 3) * 2;
        size_t o0 = (size_t)(b * SS + row0) * 2048 + h * 128 + d;
        size_t o1 = o0 + (size_t)8 * 2048;
        *(__half2*)(Oh + o0) = __floats2half2_rn(accO[nf][0] * inv0, accO[nf][1] * inv0);
        *(__half2*)(Oh + o1) = __floats2half2_rn(accO[nf][2] * inv1, accO[nf][3] * inv1);
    }
}

// ======================= launch =======================
extern "C" void kernel_launch(void* const* d_in, const int* in_sizes, int n_in,
                              void* d_out, int out_size)
{
    const int*   positions = (const int*)  d_in[0];
    const float* hidden    = (const float*)d_in[1];
    const float* residual  = (const float*)d_in[2];
    const float* ln1       = (const float*)d_in[3];
    const float* ln2       = (const float*)d_in[4];
    const float* wq        = (const float*)d_in[5];
    const float* bq        = (const float*)d_in[6];
    const float* wk        = (const float*)d_in[7];
    const float* bk        = (const float*)d_in[8];
    const float* wv        = (const float*)d_in[9];
    const float* bv        = (const float*)d_in[10];
    const float* wo        = (const float*)d_in[11];
    const float* wgu       = (const float*)d_in[12];
    const float* wd        = (const float*)d_in[13];

    float* out_h   = (float*)d_out;
    float* out_res = out_h + (size_t)out_size / 2;

    float *res1, *qkv;
    __half *xn, *at, *hattn, *h2, *ac, *Qf, *Kf, *Vh;
    __half *qkvT, *woT, *guT, *wdT;
    cudaGetSymbolAddress((void**)&res1,  g_res1);
    cudaGetSymbolAddress((void**)&qkv,   g_qkv);
    cudaGetSymbolAddress((void**)&xn,    g_xn);
    cudaGetSymbolAddress((void**)&at,    g_at);
    cudaGetSymbolAddress((void**)&hattn, g_hattn);
    cudaGetSymbolAddress((void**)&h2,    g_h2);
    cudaGetSymbolAddress((void**)&ac,    g_ac);
    cudaGetSymbolAddress((void**)&Qf,    g_Qf);
    cudaGetSymbolAddress((void**)&Kf,    g_Kf);
    cudaGetSymbolAddress((void**)&Vh,    g_Vh);
    cudaGetSymbolAddress((void**)&qkvT,  g_qkvT);
    cudaGetSymbolAddress((void**)&woT,   g_woT);
    cudaGetSymbolAddress((void**)&guT,   g_guT);
    cudaGetSymbolAddress((void**)&wdT,   g_wdT);

    cudaFuncSetAttribute(gemm_mma<0>, cudaFuncAttributeMaxDynamicSharedMemorySize, GEMM_SMEM);
    cudaFuncSetAttribute(gemm_mma<1>, cudaFuncAttributeMaxDynamicSharedMemorySize, GEMM_SMEM);
    cudaFuncSetAttribute(gemm_mma<2>, cudaFuncAttributeMaxDynamicSharedMemorySize, GEMM_SMEM);
    cudaFuncSetAttribute(gemm_mma<3>, cudaFuncAttributeMaxDynamicSharedMemorySize, GEMM_SMEM);
    cudaFuncSetAttribute(flash_mma, cudaFuncAttributeMaxDynamicSharedMemorySize, FLASH_SMEM);

    // 0. weight preprocessing (single fp16)
    wsplit_qkv_kernel<<<dim3(128, 64), dim3(32,8)>>>(wq, wk, wv, qkvT);
    wsplit_kernel<<<dim3(64, 64), dim3(32,8)>>>(wo, woT, NHQ*HD, HH);
    wsplit_gu_kernel<<<dim3(256, 64), dim3(32,8)>>>(wgu, guT);
    wsplit_kernel<<<dim3(64, 256), dim3(32,8)>>>(wd, wdT, INTER, HH);

    // 1. res1 + rmsnorm -> fp16
    add_rmsnorm_kernel<<<TT, 256>>>(hidden, residual, ln1, res1, xn);

    // 2. fused QKV projection (fp32 out, bias)
    gemm_mma<1><<<dim3(32, 32), 256, GEMM_SMEM>>>(xn, qkvT,
        bq, bk, bv, qkv, nullptr, TT, 4096, HH);

    // 3. RoPE -> single fp16 Q,K ; V transpose -> fp16
    qkconv_kernel<<<(TT * 24 * 64) / 256, 256>>>(qkv, positions, Qf, Kf);
    vconv_kernel<<<dim3(SS/32, HD/32, BB*NKV), dim3(32,8)>>>(qkv, Vh);

    // 4. flash attention (occ 2) -> fp16 at
    flash_mma<<<dim3(SS/128, NHQ, BB), 256, FLASH_SMEM>>>(Qf, Kf, Vh, at);

    // 5. output projection -> fp16 hattn
    gemm_mma<3><<<dim3(16, 32), 256, GEMM_SMEM>>>(at, woT,
        nullptr, nullptr, nullptr, nullptr, hattn, TT, HH, NHQ*HD);

    // 6. res2 + rmsnorm (fp16 + fp32 in) -> fp16
    add_rmsnorm_h_kernel<<<TT, 256>>>(hattn, res1, ln2, out_res, h2);

    // 7. gate_up GEMM + fused SwiGLU -> fp16 act
    gemm_mma<2><<<dim3(128, 32), 256, GEMM_SMEM>>>(h2, guT,
        nullptr, nullptr, nullptr, nullptr, ac, TT, 16384, HH);

    // 8. down GEMM -> out first half (fp32)
    gemm_mma<0><<<dim3(16, 32), 256, GEMM_SMEM>>>(ac, wdT,
        nullptr, nullptr, nullptr, out_h, nullptr, TT, HH, INTER);
}